// round 10
// baseline (speedup 1.0000x reference)
#include <cuda_runtime.h>
#include <cuda_bf16.h>
#include <cuda_fp8.h>
#include <cstdint>
#include <cstddef>

// ============================================================================
// Problem constants (shapes fixed by the dataset)
// ============================================================================
static constexpr int KDIM = 4096;   // inner dim
static constexpr int NDIM = 4096;   // out features
static constexpr int MMAX = 8192;   // 4*2048 rows

// bf16 scratch for quantized activations / weights (device globals: no alloc)
__device__ __align__(1024) __nv_bfloat16 g_xq[(size_t)MMAX * KDIM];
__device__ __align__(1024) __nv_bfloat16 g_wq[(size_t)NDIM * KDIM];

#define DINL static __device__ __forceinline__

DINL uint32_t smem_u32(const void* p) {
    uint32_t a;
    asm("{ .reg .u64 t; cvta.to.shared.u64 t, %1; cvt.u32.u64 %0, t; }"
        : "=r"(a) : "l"(p));
    return a;
}
DINL void cp16(uint32_t s, const void* g) {
    asm volatile("cp.async.cg.shared.global [%0], [%1], 16;" :: "r"(s), "l"(g));
}
DINL void cp_commit() { asm volatile("cp.async.commit_group;" ::: "memory"); }
DINL void cp_wait1()  { asm volatile("cp.async.wait_group 1;" ::: "memory"); }

DINL void ldmx4(uint32_t* r, uint32_t addr) {
    asm volatile("ldmatrix.sync.aligned.m8n8.x4.shared.b16 {%0,%1,%2,%3}, [%4];"
                 : "=r"(r[0]), "=r"(r[1]), "=r"(r[2]), "=r"(r[3]) : "r"(addr));
}
DINL void mma_bf16(float* c, const uint32_t* a, const uint32_t* b) {
    asm volatile(
        "mma.sync.aligned.m16n8k16.row.col.f32.bf16.bf16.f32 "
        "{%0,%1,%2,%3}, {%4,%5,%6,%7}, {%8,%9}, {%0,%1,%2,%3};"
        : "+f"(c[0]), "+f"(c[1]), "+f"(c[2]), "+f"(c[3])
        : "r"(a[0]), "r"(a[1]), "r"(a[2]), "r"(a[3]), "r"(b[0]), "r"(b[1]));
}

// ============================================================================
// Kernel 1: fused RHT (sign diag + 16-pt Hadamard) + NVFP4 quant-dequant -> bf16
// One thread per 16-element block. Single launch covers x then weight.
// ============================================================================
__global__ void __launch_bounds__(256) quant_rht_kernel(
    const float* __restrict__ inx, const float* __restrict__ inw,
    const float* __restrict__ signs,
    __nv_bfloat16* __restrict__ outx, __nv_bfloat16* __restrict__ outw,
    int nblk_x, int nblk_tot)
{
    int b = blockIdx.x * blockDim.x + threadIdx.x;
    if (b >= nblk_tot) return;

    const float* in;
    __nv_bfloat16* out;
    int bb;
    if (b < nblk_x) { in = inx; out = outx; bb = b; }
    else            { in = inw; out = outw; bb = b - nblk_x; }

    float v[16];
    const float4* p = reinterpret_cast<const float4*>(in) + (size_t)bb * 4;
    const float4* sp = reinterpret_cast<const float4*>(signs);
#pragma unroll
    for (int i = 0; i < 4; i++) {
        float4 t = p[i];
        float4 s = sp[i];
        v[4 * i + 0] = t.x * s.x; v[4 * i + 1] = t.y * s.y;
        v[4 * i + 2] = t.z * s.z; v[4 * i + 3] = t.w * s.w;
    }

    // Sylvester FWHT (matches np.block([[H,H],[H,-H]]) doubling), then /sqrt(16)
#pragma unroll
    for (int h = 1; h < 16; h <<= 1) {
#pragma unroll
        for (int i = 0; i < 16; i++) {
            if ((i & h) == 0) {
                float a = v[i], c = v[i + h];
                v[i] = a + c; v[i + h] = a - c;
            }
        }
    }
    float amax = 0.f;
#pragma unroll
    for (int i = 0; i < 16; i++) { v[i] *= 0.25f; amax = fmaxf(amax, fabsf(v[i])); }

    // E4M3 block scale, exactly like reference: rn-to-e4m3(amax/6)
    float scale = (float)__nv_fp8_e4m3(__fdiv_rn(amax, 6.0f));

    __nv_bfloat16 o[16];
    if (scale == 0.0f) {
#pragma unroll
        for (int i = 0; i < 16; i++) o[i] = __float2bfloat16_rn(0.0f);
    } else {
        // thresholds mid*scale: |v| > mid*scale  <=>  rn(|v|/scale) > mid
        const float t0 = 0.25f * scale, t1 = 0.75f * scale, t2 = 1.25f * scale,
                    t3 = 1.75f * scale, t4 = 2.5f * scale,  t5 = 3.5f * scale,
                    t6 = 5.0f * scale;
#pragma unroll
        for (int i = 0; i < 16; i++) {
            float av = fabsf(v[i]);
            float q = 0.0f;
            q = (av > t0) ? 0.5f : q;
            q = (av > t1) ? 1.0f : q;
            q = (av > t2) ? 1.5f : q;
            q = (av > t3) ? 2.0f : q;
            q = (av > t4) ? 3.0f : q;
            q = (av > t5) ? 4.0f : q;
            q = (av > t6) ? 6.0f : q;
            o[i] = __float2bfloat16_rn(copysignf(q * scale, v[i]));  // exact in bf16
        }
    }

    uint32_t w[8];
#pragma unroll
    for (int i = 0; i < 8; i++) {
        __nv_bfloat162 t = __halves2bfloat162(o[2 * i], o[2 * i + 1]);
        w[i] = *reinterpret_cast<uint32_t*>(&t);
    }
    uint4* dst = reinterpret_cast<uint4*>(out) + (size_t)bb * 2;
    dst[0] = make_uint4(w[0], w[1], w[2], w[3]);
    dst[1] = make_uint4(w[4], w[5], w[6], w[7]);
}

// ============================================================================
// Kernel 2: bf16 mma.sync GEMM  out[M,N] = A[M,K] * B[N,K]^T + bias
// BM=BN=128, BK=64 (128B rows), 3-stage cp.async pipeline, XOR-16B swizzle.
// 16 warps: 4(M) x 4(N); warp tile 32x32. 2 CTAs per SM -> 32 warps/SM
// (8 per SMSP): HMMA service queue outlasts any warp's LDSM phase.
// Register budget: 64/thread (1024 thr/SM) -> XOR-incremental LDSM addressing.
// ============================================================================
static constexpr int BM = 128, BN = 128, BK = 64, NST = 3;
static constexpr int NTHREADS = 512;
static constexpr uint32_t TILE_BYTES = 128 * 128;           // 16 KB
static constexpr uint32_t STAGE_BYTES = 2 * TILE_BYTES;     // A + B = 32 KB
static constexpr uint32_t OFF_BIAS = NST * STAGE_BYTES;     // 98304
static constexpr uint32_t SMEM_DYN = OFF_BIAS + BN * 4;     // 98816

__global__ void __launch_bounds__(NTHREADS, 2) gemm_bf16_kernel(
    const __nv_bfloat16* __restrict__ A,   // [M, K] bf16
    const __nv_bfloat16* __restrict__ B,   // [N, K] bf16
    const float* __restrict__ bias,
    float* __restrict__ out, int m_tiles)
{
    extern __shared__ __align__(128) char smem[];
    const uint32_t sbase = smem_u32(smem);
    float* sbias = reinterpret_cast<float*>(smem + OFF_BIAS);

    const int tid = threadIdx.x;
    const int wid = tid >> 5, lane = tid & 31;
    const int wm = wid >> 2, wn = wid & 3;   // 4 x 4 warps, warp tile 32x32

    // CTA rasterization: supertiles of 16 mt x 16 nt (256 CTAs) for L2 reuse
    int bid = blockIdx.x;
    int mt_idx, nt_idx;
    if ((m_tiles & 15) == 0) {
        int s = bid >> 8, r = bid & 255;     // m_tiles=64, n_tiles=32 -> s in 0..7
        mt_idx = ((s & 3) << 4) | (r & 15);
        nt_idx = ((s >> 2) << 4) | (r >> 4);
    } else {
        mt_idx = bid % m_tiles;
        nt_idx = bid / m_tiles;
    }
    const int m0 = mt_idx * BM, n0 = nt_idx * BN;

    // bias -> smem
    if (tid < BN) sbias[tid] = bias[n0 + tid];

    // ---- cp.async fill (A: 2 rows/thread, B: 2 rows/thread, 16B each) ----
    const int frow = tid >> 3;        // 0..63
    const int fcu  = tid & 7;         // 16B unit 0..7
    const __nv_bfloat16* gA0 = A + (size_t)(m0 + frow) * KDIM + fcu * 8;
    const __nv_bfloat16* gB0 = B + (size_t)(n0 + frow) * KDIM + fcu * 8;
    // loop-invariant smem store offsets (same r pattern for A and B)
    uint32_t soff0, soff1;
    {
        int r0 = frow,      x0 = r0 & 7;
        int r1 = frow + 64, x1 = r1 & 7;
        soff0 = r0 * 128 + ((fcu ^ x0) << 4);
        soff1 = r1 * 128 + ((fcu ^ x1) << 4);
    }

    auto fill_stage = [&](int stage, int kc) {
        uint32_t sa = sbase + stage * STAGE_BYTES;
        uint32_t sb = sa + TILE_BYTES;
        const __nv_bfloat16* ga = gA0 + kc * BK;
        const __nv_bfloat16* gb = gB0 + kc * BK;
        cp16(sa + soff0, ga);
        cp16(sa + soff1, ga + (size_t)64 * KDIM);
        cp16(sb + soff0, gb);
        cp16(sb + soff1, gb + (size_t)64 * KDIM);
    };

    const int KCH = KDIM / BK;   // 64
    fill_stage(0, 0); cp_commit();
    fill_stage(1, 1); cp_commit();

    float c[2][4][4];
#pragma unroll
    for (int i = 0; i < 2; i++)
#pragma unroll
        for (int j = 0; j < 4; j++)
#pragma unroll
            for (int k = 0; k < 4; k++) c[i][j][k] = 0.f;

    // XOR-incremental ldmatrix addressing:
    //   addr(r, ks) = (stage_base + C_r) ^ (ks << 5)
    //   C_r = r*128 + ((uoff ^ (x&1)) << 4) + ((x&6) << 4),  x = r & 7
    const int a_r_in16 = lane & 15;
    const int a_uoff   = lane >> 4;          // 0 or 1
    const int b_r_in16 = (lane & 7) + ((lane >> 4) << 3);
    const int b_uoff   = (lane >> 3) & 1;

    uint32_t aC[2], bC[2];
#pragma unroll
    for (int mt = 0; mt < 2; mt++) {
        int r = wm * 32 + mt * 16 + a_r_in16, x = r & 7;
        aC[mt] = r * 128 + ((a_uoff ^ (x & 1)) << 4) + ((x & 6) << 4);
    }
#pragma unroll
    for (int nh = 0; nh < 2; nh++) {
        int r = wn * 32 + nh * 16 + b_r_in16, x = r & 7;
        bC[nh] = r * 128 + ((b_uoff ^ (x & 1)) << 4) + ((x & 6) << 4);
    }

#pragma unroll 1
    for (int it = 0; it < KCH; it++) {
        cp_wait1();
        __syncthreads();
        if (it + 2 < KCH) fill_stage((it + 2) % NST, it + 2);
        cp_commit();   // empty group near tail keeps wait_group accounting right

        uint32_t sa = sbase + (it % NST) * STAGE_BYTES;
        uint32_t sb = sa + TILE_BYTES;
        uint32_t aBase0 = sa + aC[0], aBase1 = sa + aC[1];
        uint32_t bBase0 = sb + bC[0], bBase1 = sb + bC[1];

#pragma unroll
        for (int ks = 0; ks < 4; ks++) {
            const uint32_t kx = (uint32_t)(ks << 5);
            uint32_t b2[2][4];
            ldmx4(b2[0], bBase0 ^ kx);
            ldmx4(b2[1], bBase1 ^ kx);
#pragma unroll
            for (int mt = 0; mt < 2; mt++) {
                uint32_t a[4];
                ldmx4(a, (mt ? aBase1 : aBase0) ^ kx);
#pragma unroll
                for (int nt = 0; nt < 4; nt++) {
                    const uint32_t bb[2] = { b2[nt >> 1][(nt & 1) * 2],
                                             b2[nt >> 1][(nt & 1) * 2 + 1] };
                    mma_bf16(c[mt][nt], a, bb);
                }
            }
        }
    }

    // ---- epilogue: direct float2 stores with bias ----
    const int er = lane >> 2;            // 0..7
    const int ec = (lane & 3) * 2;       // 0,2,4,6
#pragma unroll
    for (int mt = 0; mt < 2; mt++) {
        int row0 = m0 + wm * 32 + mt * 16 + er;
#pragma unroll
        for (int nt = 0; nt < 4; nt++) {
            int colL = wn * 32 + nt * 8 + ec;       // local col in [0,128)
            int col  = n0 + colL;
            float b0 = sbias[colL], b1 = sbias[colL + 1];
            float2 v0 = make_float2(c[mt][nt][0] + b0, c[mt][nt][1] + b1);
            float2 v1 = make_float2(c[mt][nt][2] + b0, c[mt][nt][3] + b1);
            *reinterpret_cast<float2*>(out + (size_t)row0 * NDIM + col) = v0;
            *reinterpret_cast<float2*>(out + (size_t)(row0 + 8) * NDIM + col) = v1;
        }
    }
}

// ============================================================================
// Host side
// ============================================================================
extern "C" void kernel_launch(void* const* d_in, const int* in_sizes, int n_in,
                              void* d_out, int out_size)
{
    const float* x        = (const float*)d_in[0];
    const float* weight   = (const float*)d_in[1];
    const float* bias     = (const float*)d_in[2];
    const float* signs_in = (const float*)d_in[3];
    // d_in[4] = signs_grad: unused in forward

    const int K = KDIM, N = NDIM;
    const int M = in_sizes[0] / K;

    __nv_bfloat16 *xq = nullptr, *wq = nullptr;
    cudaGetSymbolAddress((void**)&xq, g_xq);
    cudaGetSymbolAddress((void**)&wq, g_wq);

    // --- quantize x and weight to bf16 scratch (single launch) ---
    int nblk_x = M * (K / 16);
    int nblk_w = N * (K / 16);
    int nblk_tot = nblk_x + nblk_w;
    quant_rht_kernel<<<(nblk_tot + 255) / 256, 256>>>(
        x, weight, signs_in, xq, wq, nblk_x, nblk_tot);

    // --- GEMM ---
    static bool attr_set = false;
    if (!attr_set) {
        cudaFuncSetAttribute(gemm_bf16_kernel,
                             cudaFuncAttributeMaxDynamicSharedMemorySize, SMEM_DYN);
        attr_set = true;
    }
    int m_tiles = M / BM;            // 64
    int n_tiles = N / BN;            // 32
    gemm_bf16_kernel<<<m_tiles * n_tiles, NTHREADS, SMEM_DYN>>>(
        xq, wq, bias, (float*)d_out, m_tiles);
}

// round 11
// speedup vs baseline: 1.0223x; 1.0223x over previous
#include <cuda_runtime.h>
#include <cuda_bf16.h>
#include <cuda_fp8.h>
#include <cstdint>
#include <cstddef>

// ============================================================================
// Problem constants (shapes fixed by the dataset)
// ============================================================================
static constexpr int KDIM = 4096;   // inner dim
static constexpr int NDIM = 4096;   // out features
static constexpr int MMAX = 8192;   // 4*2048 rows

// bf16 scratch for quantized activations / weights (device globals: no alloc)
__device__ __align__(1024) __nv_bfloat16 g_xq[(size_t)MMAX * KDIM];
__device__ __align__(1024) __nv_bfloat16 g_wq[(size_t)NDIM * KDIM];

#define DINL static __device__ __forceinline__

DINL uint32_t smem_u32(const void* p) {
    uint32_t a;
    asm("{ .reg .u64 t; cvta.to.shared.u64 t, %1; cvt.u32.u64 %0, t; }"
        : "=r"(a) : "l"(p));
    return a;
}
DINL void cp16(uint32_t s, const void* g) {
    asm volatile("cp.async.cg.shared.global [%0], [%1], 16;" :: "r"(s), "l"(g));
}
DINL void cp_commit() { asm volatile("cp.async.commit_group;" ::: "memory"); }
DINL void cp_wait1()  { asm volatile("cp.async.wait_group 1;" ::: "memory"); }

DINL void ldmx4(uint32_t* r, uint32_t addr) {
    asm volatile("ldmatrix.sync.aligned.m8n8.x4.shared.b16 {%0,%1,%2,%3}, [%4];"
                 : "=r"(r[0]), "=r"(r[1]), "=r"(r[2]), "=r"(r[3]) : "r"(addr));
}
DINL void mma_bf16(float* c, const uint32_t* a, const uint32_t* b) {
    asm volatile(
        "mma.sync.aligned.m16n8k16.row.col.f32.bf16.bf16.f32 "
        "{%0,%1,%2,%3}, {%4,%5,%6,%7}, {%8,%9}, {%0,%1,%2,%3};"
        : "+f"(c[0]), "+f"(c[1]), "+f"(c[2]), "+f"(c[3])
        : "r"(a[0]), "r"(a[1]), "r"(a[2]), "r"(a[3]), "r"(b[0]), "r"(b[1]));
}

// ============================================================================
// Kernel 1: fused RHT (sign diag + 16-pt Hadamard) + NVFP4 quant-dequant -> bf16
// One thread per 16-element block. Single launch covers x then weight.
// ============================================================================
__global__ void __launch_bounds__(256) quant_rht_kernel(
    const float* __restrict__ inx, const float* __restrict__ inw,
    const float* __restrict__ signs,
    __nv_bfloat16* __restrict__ outx, __nv_bfloat16* __restrict__ outw,
    int nblk_x, int nblk_tot)
{
    int b = blockIdx.x * blockDim.x + threadIdx.x;
    if (b >= nblk_tot) return;

    const float* in;
    __nv_bfloat16* out;
    int bb;
    if (b < nblk_x) { in = inx; out = outx; bb = b; }
    else            { in = inw; out = outw; bb = b - nblk_x; }

    float v[16];
    const float4* p = reinterpret_cast<const float4*>(in) + (size_t)bb * 4;
    const float4* sp = reinterpret_cast<const float4*>(signs);
#pragma unroll
    for (int i = 0; i < 4; i++) {
        float4 t = p[i];
        float4 s = sp[i];
        v[4 * i + 0] = t.x * s.x; v[4 * i + 1] = t.y * s.y;
        v[4 * i + 2] = t.z * s.z; v[4 * i + 3] = t.w * s.w;
    }

    // Sylvester FWHT (matches np.block([[H,H],[H,-H]]) doubling), then /sqrt(16)
#pragma unroll
    for (int h = 1; h < 16; h <<= 1) {
#pragma unroll
        for (int i = 0; i < 16; i++) {
            if ((i & h) == 0) {
                float a = v[i], c = v[i + h];
                v[i] = a + c; v[i + h] = a - c;
            }
        }
    }
    float amax = 0.f;
#pragma unroll
    for (int i = 0; i < 16; i++) { v[i] *= 0.25f; amax = fmaxf(amax, fabsf(v[i])); }

    // E4M3 block scale, exactly like reference: rn-to-e4m3(amax/6)
    float scale = (float)__nv_fp8_e4m3(__fdiv_rn(amax, 6.0f));

    __nv_bfloat16 o[16];
    if (scale == 0.0f) {
#pragma unroll
        for (int i = 0; i < 16; i++) o[i] = __float2bfloat16_rn(0.0f);
    } else {
        // thresholds mid*scale: |v| > mid*scale  <=>  rn(|v|/scale) > mid
        const float t0 = 0.25f * scale, t1 = 0.75f * scale, t2 = 1.25f * scale,
                    t3 = 1.75f * scale, t4 = 2.5f * scale,  t5 = 3.5f * scale,
                    t6 = 5.0f * scale;
#pragma unroll
        for (int i = 0; i < 16; i++) {
            float av = fabsf(v[i]);
            float q = 0.0f;
            q = (av > t0) ? 0.5f : q;
            q = (av > t1) ? 1.0f : q;
            q = (av > t2) ? 1.5f : q;
            q = (av > t3) ? 2.0f : q;
            q = (av > t4) ? 3.0f : q;
            q = (av > t5) ? 4.0f : q;
            q = (av > t6) ? 6.0f : q;
            o[i] = __float2bfloat16_rn(copysignf(q * scale, v[i]));  // exact in bf16
        }
    }

    uint32_t w[8];
#pragma unroll
    for (int i = 0; i < 8; i++) {
        __nv_bfloat162 t = __halves2bfloat162(o[2 * i], o[2 * i + 1]);
        w[i] = *reinterpret_cast<uint32_t*>(&t);
    }
    uint4* dst = reinterpret_cast<uint4*>(out) + (size_t)bb * 2;
    dst[0] = make_uint4(w[0], w[1], w[2], w[3]);
    dst[1] = make_uint4(w[4], w[5], w[6], w[7]);
}

// ============================================================================
// Kernel 2: bf16 mma.sync GEMM  out[M,N] = A[M,K] * B[N,K]^T + bias
// R8 config (best measured): BM=BN=128, BK=64, 3-stage cp.async, occupancy 2,
// 8 warps 2(M)x4(N), warp tile 64x32. This round: XOR-incremental ldmatrix
// addressing (addr = base ^ (ks<<5)) + hoisted fill offsets to cut alu%.
// ============================================================================
static constexpr int BM = 128, BN = 128, BK = 64, NST = 3;
static constexpr uint32_t TILE_BYTES = 128 * 128;           // 16 KB
static constexpr uint32_t STAGE_BYTES = 2 * TILE_BYTES;     // A + B = 32 KB
static constexpr uint32_t OFF_BIAS = NST * STAGE_BYTES;     // 98304
static constexpr uint32_t SMEM_DYN = OFF_BIAS + BN * 4;     // 98816

__global__ void __launch_bounds__(256, 2) gemm_bf16_kernel(
    const __nv_bfloat16* __restrict__ A,   // [M, K] bf16
    const __nv_bfloat16* __restrict__ B,   // [N, K] bf16
    const float* __restrict__ bias,
    float* __restrict__ out, int m_tiles)
{
    extern __shared__ __align__(128) char smem[];
    const uint32_t sbase = smem_u32(smem);
    float* sbias = reinterpret_cast<float*>(smem + OFF_BIAS);

    const int tid = threadIdx.x;
    const int wid = tid >> 5, lane = tid & 31;
    const int wm = wid >> 2, wn = wid & 3;   // 2 x 4 warps, warp tile 64x32

    // CTA rasterization: supertiles of 16 mt x 16 nt (256 CTAs) for L2 reuse
    int bid = blockIdx.x;
    int mt_idx, nt_idx;
    if ((m_tiles & 15) == 0) {
        int s = bid >> 8, r = bid & 255;          // m_tiles=64, n_tiles=32 -> s in 0..7
        mt_idx = ((s & 3) << 4) | (r & 15);
        nt_idx = ((s >> 2) << 4) | (r >> 4);
    } else {
        mt_idx = bid % m_tiles;
        nt_idx = bid / m_tiles;
    }
    const int m0 = mt_idx * BM, n0 = nt_idx * BN;

    // bias -> smem
    if (tid < BN) sbias[tid] = bias[n0 + tid];

    // ---- cp.async fill helper (each thread: 4 A rows + 4 B rows, 16B each) ----
    const int frow = tid >> 3;        // 0..31
    const int fcu  = tid & 7;         // 16B unit 0..7
    const __nv_bfloat16* gA0 = A + (size_t)(m0 + frow) * KDIM + fcu * 8;
    const __nv_bfloat16* gB0 = B + (size_t)(n0 + frow) * KDIM + fcu * 8;
    // loop-invariant smem store offsets
    uint32_t soff[4];
#pragma unroll
    for (int p = 0; p < 4; p++) {
        int r = frow + p * 32;
        soff[p] = r * 128 + ((fcu ^ (r & 7)) << 4);
    }

    auto fill_stage = [&](int stage, int kc) {
        uint32_t sa = sbase + stage * STAGE_BYTES;
        uint32_t sb = sa + TILE_BYTES;
        const __nv_bfloat16* ga = gA0 + kc * BK;
        const __nv_bfloat16* gb = gB0 + kc * BK;
#pragma unroll
        for (int p = 0; p < 4; p++) {
            cp16(sa + soff[p], ga + (size_t)(p * 32) * KDIM);
            cp16(sb + soff[p], gb + (size_t)(p * 32) * KDIM);
        }
    };

    const int KCH = KDIM / BK;   // 64
    fill_stage(0, 0); cp_commit();
    fill_stage(1, 1); cp_commit();

    float c[4][4][4];
#pragma unroll
    for (int i = 0; i < 4; i++)
#pragma unroll
        for (int j = 0; j < 4; j++)
#pragma unroll
            for (int k = 0; k < 4; k++) c[i][j][k] = 0.f;

    // XOR-incremental ldmatrix addressing:
    //   addr(r, ks) = (stage_base + C_r) ^ (ks << 5)
    //   C_r = r*128 + ((uoff ^ (x&1)) << 4) + ((x&6) << 4),  x = r & 7
    const int a_r_in16 = lane & 15;
    const int a_uoff   = lane >> 4;          // 0 or 1
    const int b_r_in16 = (lane & 7) + ((lane >> 4) << 3);
    const int b_uoff   = (lane >> 3) & 1;

    uint32_t aC[4], bC[2];
#pragma unroll
    for (int mt = 0; mt < 4; mt++) {
        int r = wm * 64 + mt * 16 + a_r_in16, x = r & 7;
        aC[mt] = r * 128 + ((a_uoff ^ (x & 1)) << 4) + ((x & 6) << 4);
    }
#pragma unroll
    for (int nh = 0; nh < 2; nh++) {
        int r = wn * 32 + nh * 16 + b_r_in16, x = r & 7;
        bC[nh] = r * 128 + ((b_uoff ^ (x & 1)) << 4) + ((x & 6) << 4);
    }

#pragma unroll 1
    for (int it = 0; it < KCH; it++) {
        cp_wait1();
        __syncthreads();
        if (it + 2 < KCH) fill_stage((it + 2) % NST, it + 2);
        cp_commit();   // empty group near tail keeps wait_group accounting right

        uint32_t sa = sbase + (it % NST) * STAGE_BYTES;
        uint32_t sb = sa + TILE_BYTES;
        uint32_t aB0 = sa + aC[0], aB1 = sa + aC[1];
        uint32_t aB2 = sa + aC[2], aB3 = sa + aC[3];
        uint32_t bB0 = sb + bC[0], bB1 = sb + bC[1];

#pragma unroll
        for (int ks = 0; ks < 4; ks++) {
            const uint32_t kx = (uint32_t)(ks << 5);
            uint32_t b2[2][4];
            ldmx4(b2[0], bB0 ^ kx);
            ldmx4(b2[1], bB1 ^ kx);
#pragma unroll
            for (int mt = 0; mt < 4; mt++) {
                uint32_t a[4];
                uint32_t ab = (mt == 0) ? aB0 : (mt == 1) ? aB1 : (mt == 2) ? aB2 : aB3;
                ldmx4(a, ab ^ kx);
#pragma unroll
                for (int nt = 0; nt < 4; nt++) {
                    const uint32_t bb[2] = { b2[nt >> 1][(nt & 1) * 2],
                                             b2[nt >> 1][(nt & 1) * 2 + 1] };
                    mma_bf16(c[mt][nt], a, bb);
                }
            }
        }
    }

    // ---- epilogue: direct float2 stores with bias ----
    const int er = lane >> 2;            // 0..7
    const int ec = (lane & 3) * 2;       // 0,2,4,6
#pragma unroll
    for (int mt = 0; mt < 4; mt++) {
        int row0 = m0 + wm * 64 + mt * 16 + er;
#pragma unroll
        for (int nt = 0; nt < 4; nt++) {
            int colL = wn * 32 + nt * 8 + ec;       // local col in [0,128)
            int col  = n0 + colL;
            float b0 = sbias[colL], b1 = sbias[colL + 1];
            float2 v0 = make_float2(c[mt][nt][0] + b0, c[mt][nt][1] + b1);
            float2 v1 = make_float2(c[mt][nt][2] + b0, c[mt][nt][3] + b1);
            *reinterpret_cast<float2*>(out + (size_t)row0 * NDIM + col) = v0;
            *reinterpret_cast<float2*>(out + (size_t)(row0 + 8) * NDIM + col) = v1;
        }
    }
}

// ============================================================================
// Host side
// ============================================================================
extern "C" void kernel_launch(void* const* d_in, const int* in_sizes, int n_in,
                              void* d_out, int out_size)
{
    const float* x        = (const float*)d_in[0];
    const float* weight   = (const float*)d_in[1];
    const float* bias     = (const float*)d_in[2];
    const float* signs_in = (const float*)d_in[3];
    // d_in[4] = signs_grad: unused in forward

    const int K = KDIM, N = NDIM;
    const int M = in_sizes[0] / K;

    __nv_bfloat16 *xq = nullptr, *wq = nullptr;
    cudaGetSymbolAddress((void**)&xq, g_xq);
    cudaGetSymbolAddress((void**)&wq, g_wq);

    // --- quantize x and weight to bf16 scratch (single launch) ---
    int nblk_x = M * (K / 16);
    int nblk_w = N * (K / 16);
    int nblk_tot = nblk_x + nblk_w;
    quant_rht_kernel<<<(nblk_tot + 255) / 256, 256>>>(
        x, weight, signs_in, xq, wq, nblk_x, nblk_tot);

    // --- GEMM ---
    static bool attr_set = false;
    if (!attr_set) {
        cudaFuncSetAttribute(gemm_bf16_kernel,
                             cudaFuncAttributeMaxDynamicSharedMemorySize, SMEM_DYN);
        attr_set = true;
    }
    int m_tiles = M / BM;            // 64
    int n_tiles = N / BN;            // 32
    gemm_bf16_kernel<<<m_tiles * n_tiles, 256, SMEM_DYN>>>(
        xq, wq, bias, (float*)d_out, m_tiles);
}

// round 12
// speedup vs baseline: 1.0562x; 1.0332x over previous
#include <cuda_runtime.h>
#include <cuda_bf16.h>
#include <cuda_fp8.h>
#include <cstdint>
#include <cstddef>

// ============================================================================
// Problem constants (shapes fixed by the dataset)
// ============================================================================
static constexpr int KDIM = 4096;   // inner dim
static constexpr int NDIM = 4096;   // out features
static constexpr int MMAX = 8192;   // 4*2048 rows

// bf16 scratch for quantized activations / weights (device globals: no alloc)
__device__ __align__(1024) __nv_bfloat16 g_xq[(size_t)MMAX * KDIM];
__device__ __align__(1024) __nv_bfloat16 g_wq[(size_t)NDIM * KDIM];

#define DINL static __device__ __forceinline__

DINL uint32_t smem_u32(const void* p) {
    uint32_t a;
    asm("{ .reg .u64 t; cvta.to.shared.u64 t, %1; cvt.u32.u64 %0, t; }"
        : "=r"(a) : "l"(p));
    return a;
}
DINL void cp16(uint32_t s, const void* g) {
    asm volatile("cp.async.cg.shared.global [%0], [%1], 16;" :: "r"(s), "l"(g));
}
DINL void cp_commit() { asm volatile("cp.async.commit_group;" ::: "memory"); }
DINL void cp_wait1()  { asm volatile("cp.async.wait_group 1;" ::: "memory"); }

DINL void ldmx4(uint32_t* r, uint32_t addr) {
    asm volatile("ldmatrix.sync.aligned.m8n8.x4.shared.b16 {%0,%1,%2,%3}, [%4];"
                 : "=r"(r[0]), "=r"(r[1]), "=r"(r[2]), "=r"(r[3]) : "r"(addr));
}
DINL void mma_bf16(float* c, const uint32_t* a, const uint32_t* b) {
    asm volatile(
        "mma.sync.aligned.m16n8k16.row.col.f32.bf16.bf16.f32 "
        "{%0,%1,%2,%3}, {%4,%5,%6,%7}, {%8,%9}, {%0,%1,%2,%3};"
        : "+f"(c[0]), "+f"(c[1]), "+f"(c[2]), "+f"(c[3])
        : "r"(a[0]), "r"(a[1]), "r"(a[2]), "r"(a[3]), "r"(b[0]), "r"(b[1]));
}

// ============================================================================
// Kernel 1: fused RHT (sign diag + 16-pt Hadamard) + NVFP4 quant-dequant -> bf16
// One thread per 16-element block. Single launch covers x then weight.
// The /sqrt(16)=0.25 normalization is folded into scale + thresholds (exact:
// power-of-2 scalings are lossless in fp32/e4m3 rounding).
// ============================================================================
__global__ void __launch_bounds__(256) quant_rht_kernel(
    const float* __restrict__ inx, const float* __restrict__ inw,
    const float* __restrict__ signs,
    __nv_bfloat16* __restrict__ outx, __nv_bfloat16* __restrict__ outw,
    int nblk_x, int nblk_tot)
{
    int b = blockIdx.x * blockDim.x + threadIdx.x;
    if (b >= nblk_tot) return;

    const float* in;
    __nv_bfloat16* out;
    int bb;
    if (b < nblk_x) { in = inx; out = outx; bb = b; }
    else            { in = inw; out = outw; bb = b - nblk_x; }

    float v[16];
    const float4* p = reinterpret_cast<const float4*>(in) + (size_t)bb * 4;
    const float4* sp = reinterpret_cast<const float4*>(signs);
#pragma unroll
    for (int i = 0; i < 4; i++) {
        float4 t = p[i];
        float4 s = sp[i];
        v[4 * i + 0] = t.x * s.x; v[4 * i + 1] = t.y * s.y;
        v[4 * i + 2] = t.z * s.z; v[4 * i + 3] = t.w * s.w;
    }

    // Sylvester FWHT (matches np.block([[H,H],[H,-H]]) doubling); raw (un-normalized)
#pragma unroll
    for (int h = 1; h < 16; h <<= 1) {
#pragma unroll
        for (int i = 0; i < 16; i++) {
            if ((i & h) == 0) {
                float a = v[i], c = v[i + h];
                v[i] = a + c; v[i + h] = a - c;
            }
        }
    }
    float amax = 0.f;
#pragma unroll
    for (int i = 0; i < 16; i++) amax = fmaxf(amax, fabsf(v[i]));

    // scaled value = v*0.25 (exact). scale = e4m3(rn((amax*0.25)/6)).
    float scale = (float)__nv_fp8_e4m3(__fdiv_rn(amax * 0.25f, 6.0f));

    __nv_bfloat16 o[16];
    if (scale == 0.0f) {
#pragma unroll
        for (int i = 0; i < 16; i++) o[i] = __float2bfloat16_rn(0.0f);
    } else {
        // thresholds on RAW |v|: |v*0.25| > mid*scale <=> |v| > mid*scale*4 (exact x4)
        const float s4 = scale * 4.0f;
        const float t0 = 0.25f * s4, t1 = 0.75f * s4, t2 = 1.25f * s4,
                    t3 = 1.75f * s4, t4 = 2.5f * s4,  t5 = 3.5f * s4,
                    t6 = 5.0f * s4;
#pragma unroll
        for (int i = 0; i < 16; i++) {
            float av = fabsf(v[i]);
            float q = 0.0f;
            q = (av > t0) ? 0.5f : q;
            q = (av > t1) ? 1.0f : q;
            q = (av > t2) ? 1.5f : q;
            q = (av > t3) ? 2.0f : q;
            q = (av > t4) ? 3.0f : q;
            q = (av > t5) ? 4.0f : q;
            q = (av > t6) ? 6.0f : q;
            o[i] = __float2bfloat16_rn(copysignf(q * scale, v[i]));  // exact in bf16
        }
    }

    uint32_t w[8];
#pragma unroll
    for (int i = 0; i < 8; i++) {
        __nv_bfloat162 t = __halves2bfloat162(o[2 * i], o[2 * i + 1]);
        w[i] = *reinterpret_cast<uint32_t*>(&t);
    }
    uint4* dst = reinterpret_cast<uint4*>(out) + (size_t)bb * 2;
    dst[0] = make_uint4(w[0], w[1], w[2], w[3]);
    dst[1] = make_uint4(w[4], w[5], w[6], w[7]);
}

// ============================================================================
// Kernel 2: bf16 mma.sync GEMM  out[M,N] = A[M,K] * B[N,K]^T + bias
// Exact R8 config (best measured): BM=BN=128, BK=64, 3-stage cp.async,
// occupancy 2, 8 warps 2(M)x4(N), warp tile 64x32, plain LDSM addressing.
// New: ks=0 fragments are loaded IMMEDIATELY after the stage sync, before the
// cp.async fill burst, so MMAs start while the fill issues underneath.
// ============================================================================
static constexpr int BM = 128, BN = 128, BK = 64, NST = 3;
static constexpr uint32_t TILE_BYTES = 128 * 128;           // 16 KB
static constexpr uint32_t STAGE_BYTES = 2 * TILE_BYTES;     // A + B = 32 KB
static constexpr uint32_t OFF_BIAS = NST * STAGE_BYTES;     // 98304
static constexpr uint32_t SMEM_DYN = OFF_BIAS + BN * 4;     // 98816

__global__ void __launch_bounds__(256, 2) gemm_bf16_kernel(
    const __nv_bfloat16* __restrict__ A,   // [M, K] bf16
    const __nv_bfloat16* __restrict__ B,   // [N, K] bf16
    const float* __restrict__ bias,
    float* __restrict__ out, int m_tiles)
{
    extern __shared__ __align__(128) char smem[];
    const uint32_t sbase = smem_u32(smem);
    float* sbias = reinterpret_cast<float*>(smem + OFF_BIAS);

    const int tid = threadIdx.x;
    const int wid = tid >> 5, lane = tid & 31;
    const int wm = wid >> 2, wn = wid & 3;   // 2 x 4 warps, warp tile 64x32

    // CTA rasterization: supertiles of 16 mt x 16 nt (256 CTAs) for L2 reuse
    int bid = blockIdx.x;
    int mt_idx, nt_idx;
    if ((m_tiles & 15) == 0) {
        int s = bid >> 8, r = bid & 255;          // m_tiles=64, n_tiles=32 -> s in 0..7
        mt_idx = ((s & 3) << 4) | (r & 15);
        nt_idx = ((s >> 2) << 4) | (r >> 4);
    } else {
        mt_idx = bid % m_tiles;
        nt_idx = bid / m_tiles;
    }
    const int m0 = mt_idx * BM, n0 = nt_idx * BN;

    // bias -> smem
    if (tid < BN) sbias[tid] = bias[n0 + tid];

    // ---- cp.async fill helper (each thread: 4 A rows + 4 B rows, 16B each) ----
    const int frow = tid >> 3;        // 0..31
    const int fcu  = tid & 7;         // 16B unit 0..7
    const __nv_bfloat16* gA0 = A + (size_t)(m0 + frow) * KDIM + fcu * 8;
    const __nv_bfloat16* gB0 = B + (size_t)(n0 + frow) * KDIM + fcu * 8;

    auto fill_stage = [&](int stage, int kc) {
        uint32_t sa = sbase + stage * STAGE_BYTES;
        uint32_t sb = sa + TILE_BYTES;
        const __nv_bfloat16* ga = gA0 + kc * BK;
        const __nv_bfloat16* gb = gB0 + kc * BK;
#pragma unroll
        for (int p = 0; p < 4; p++) {
            int r = frow + p * 32;
            uint32_t soff = r * 128 + ((fcu ^ (r & 7)) << 4);
            cp16(sa + soff, ga + (size_t)(p * 32) * KDIM);
            cp16(sb + soff, gb + (size_t)(p * 32) * KDIM);
        }
    };

    const int KCH = KDIM / BK;   // 64
    fill_stage(0, 0); cp_commit();
    fill_stage(1, 1); cp_commit();

    float c[4][4][4];
#pragma unroll
    for (int i = 0; i < 4; i++)
#pragma unroll
        for (int j = 0; j < 4; j++)
#pragma unroll
            for (int k = 0; k < 4; k++) c[i][j][k] = 0.f;

    // ldmatrix lane address components (R8 plain addressing)
    const int a_r_in16 = lane & 15;
    const int a_uoff   = lane >> 4;          // 0 or 1
    const int b_r_in16 = (lane & 7) + ((lane >> 4) << 3);
    const int b_uoff   = (lane >> 3) & 1;

#pragma unroll 1
    for (int it = 0; it < KCH; it++) {
        cp_wait1();
        __syncthreads();

        uint32_t sa = sbase + (it % NST) * STAGE_BYTES;
        uint32_t sb = sa + TILE_BYTES;

        // ---- ks=0 fragments FIRST: get MMAs in flight before the fill burst ----
        uint32_t a0[4][4], b0[2][4];
#pragma unroll
        for (int mt = 0; mt < 4; mt++) {
            int r = wm * 64 + mt * 16 + a_r_in16;
            ldmx4(a0[mt], sa + r * 128 + ((a_uoff ^ (r & 7)) << 4));
        }
#pragma unroll
        for (int nh = 0; nh < 2; nh++) {
            int r = wn * 32 + nh * 16 + b_r_in16;
            ldmx4(b0[nh], sb + r * 128 + ((b_uoff ^ (r & 7)) << 4));
        }

        // ---- fill next stage (issues overlap the ks=0 MMA wave) ----
        if (it + 2 < KCH) fill_stage((it + 2) % NST, it + 2);
        cp_commit();   // empty group near tail keeps wait_group accounting right

        // ks = 0 MMAs from preloaded fragments
#pragma unroll
        for (int mt = 0; mt < 4; mt++) {
#pragma unroll
            for (int nt = 0; nt < 4; nt++) {
                const uint32_t bb[2] = { b0[nt >> 1][(nt & 1) * 2],
                                         b0[nt >> 1][(nt & 1) * 2 + 1] };
                mma_bf16(c[mt][nt], a0[mt], bb);
            }
        }

        // ks = 1..3
#pragma unroll
        for (int ks = 1; ks < 4; ks++) {
            uint32_t a[4][4], b2[2][4];
#pragma unroll
            for (int mt = 0; mt < 4; mt++) {
                int r = wm * 64 + mt * 16 + a_r_in16;
                int u = ks * 2 + a_uoff;
                ldmx4(a[mt], sa + r * 128 + ((u ^ (r & 7)) << 4));
            }
#pragma unroll
            for (int nh = 0; nh < 2; nh++) {
                int r = wn * 32 + nh * 16 + b_r_in16;
                int u = ks * 2 + b_uoff;
                ldmx4(b2[nh], sb + r * 128 + ((u ^ (r & 7)) << 4));
            }
#pragma unroll
            for (int mt = 0; mt < 4; mt++) {
#pragma unroll
                for (int nt = 0; nt < 4; nt++) {
                    const uint32_t bb[2] = { b2[nt >> 1][(nt & 1) * 2],
                                             b2[nt >> 1][(nt & 1) * 2 + 1] };
                    mma_bf16(c[mt][nt], a[mt], bb);
                }
            }
        }
    }

    // ---- epilogue: direct float2 stores with bias ----
    const int er = lane >> 2;            // 0..7
    const int ec = (lane & 3) * 2;       // 0,2,4,6
#pragma unroll
    for (int mt = 0; mt < 4; mt++) {
        int row0 = m0 + wm * 64 + mt * 16 + er;
#pragma unroll
        for (int nt = 0; nt < 4; nt++) {
            int colL = wn * 32 + nt * 8 + ec;       // local col in [0,128)
            int col  = n0 + colL;
            float b0v = sbias[colL], b1v = sbias[colL + 1];
            float2 v0 = make_float2(c[mt][nt][0] + b0v, c[mt][nt][1] + b1v);
            float2 v1 = make_float2(c[mt][nt][2] + b0v, c[mt][nt][3] + b1v);
            *reinterpret_cast<float2*>(out + (size_t)row0 * NDIM + col) = v0;
            *reinterpret_cast<float2*>(out + (size_t)(row0 + 8) * NDIM + col) = v1;
        }
    }
}

// ============================================================================
// Host side
// ============================================================================
extern "C" void kernel_launch(void* const* d_in, const int* in_sizes, int n_in,
                              void* d_out, int out_size)
{
    const float* x        = (const float*)d_in[0];
    const float* weight   = (const float*)d_in[1];
    const float* bias     = (const float*)d_in[2];
    const float* signs_in = (const float*)d_in[3];
    // d_in[4] = signs_grad: unused in forward

    const int K = KDIM, N = NDIM;
    const int M = in_sizes[0] / K;

    __nv_bfloat16 *xq = nullptr, *wq = nullptr;
    cudaGetSymbolAddress((void**)&xq, g_xq);
    cudaGetSymbolAddress((void**)&wq, g_wq);

    // --- quantize x and weight to bf16 scratch (single launch) ---
    int nblk_x = M * (K / 16);
    int nblk_w = N * (K / 16);
    int nblk_tot = nblk_x + nblk_w;
    quant_rht_kernel<<<(nblk_tot + 255) / 256, 256>>>(
        x, weight, signs_in, xq, wq, nblk_x, nblk_tot);

    // --- GEMM ---
    static bool attr_set = false;
    if (!attr_set) {
        cudaFuncSetAttribute(gemm_bf16_kernel,
                             cudaFuncAttributeMaxDynamicSharedMemorySize, SMEM_DYN);
        attr_set = true;
    }
    int m_tiles = M / BM;            // 64
    int n_tiles = N / BN;            // 32
    gemm_bf16_kernel<<<m_tiles * n_tiles, 256, SMEM_DYN>>>(
        xq, wq, bias, (float*)d_out, m_tiles);
}

// round 14
// speedup vs baseline: 1.1175x; 1.0580x over previous
#include <cuda_runtime.h>
#include <cuda.h>
#include <cuda_bf16.h>
#include <cuda_fp8.h>
#include <cstdint>
#include <cstddef>

// ============================================================================
// Problem constants (shapes fixed by the dataset)
// ============================================================================
static constexpr int KDIM = 4096;   // inner dim
static constexpr int NDIM = 4096;   // out features
static constexpr int MMAX = 8192;   // 4*2048 rows

// bf16 scratch for quantized activations / weights (device globals: no alloc)
__device__ __align__(1024) __nv_bfloat16 g_xq[(size_t)MMAX * KDIM];
__device__ __align__(1024) __nv_bfloat16 g_wq[(size_t)NDIM * KDIM];

#define DINL static __device__ __forceinline__

DINL uint32_t smem_u32(const void* p) {
    uint32_t a;
    asm("{ .reg .u64 t; cvta.to.shared.u64 t, %1; cvt.u32.u64 %0, t; }"
        : "=r"(a) : "l"(p));
    return a;
}
DINL void mbar_init(uint32_t a, uint32_t cnt) {
    asm volatile("mbarrier.init.shared.b64 [%0], %1;" :: "r"(a), "r"(cnt) : "memory");
}
DINL void mbar_expect_tx(uint32_t a, uint32_t bytes) {
    asm volatile("mbarrier.arrive.expect_tx.shared.b64 _, [%0], %1;"
                 :: "r"(a), "r"(bytes) : "memory");
}
DINL void mbar_wait(uint32_t a, uint32_t parity) {
    asm volatile(
        "{\n\t.reg .pred P;\n\t"
        "LAB_W_%=:\n\t"
        "mbarrier.try_wait.parity.acquire.cta.shared::cta.b64 P, [%0], %1, 0x989680;\n\t"
        "@P bra LAB_D_%=;\n\t"
        "bra LAB_W_%=;\n\t"
        "LAB_D_%=:\n\t}"
        :: "r"(a), "r"(parity) : "memory");
}
DINL void tma2d(uint32_t dst, const CUtensorMap* tm, int cx, int cy, uint32_t bar) {
    asm volatile(
        "cp.async.bulk.tensor.2d.shared::cta.global.tile.mbarrier::complete_tx::bytes "
        "[%0], [%1, {%2, %3}], [%4];"
        :: "r"(dst), "l"(tm), "r"(cx), "r"(cy), "r"(bar) : "memory");
}
DINL void fence_proxy() { asm volatile("fence.proxy.async.shared::cta;" ::: "memory"); }

DINL void ldmx4(uint32_t* r, uint32_t addr) {
    asm volatile("ldmatrix.sync.aligned.m8n8.x4.shared.b16 {%0,%1,%2,%3}, [%4];"
                 : "=r"(r[0]), "=r"(r[1]), "=r"(r[2]), "=r"(r[3]) : "r"(addr));
}
DINL void mma_bf16(float* c, const uint32_t* a, const uint32_t* b) {
    asm volatile(
        "mma.sync.aligned.m16n8k16.row.col.f32.bf16.bf16.f32 "
        "{%0,%1,%2,%3}, {%4,%5,%6,%7}, {%8,%9}, {%0,%1,%2,%3};"
        : "+f"(c[0]), "+f"(c[1]), "+f"(c[2]), "+f"(c[3])
        : "r"(a[0]), "r"(a[1]), "r"(a[2]), "r"(a[3]), "r"(b[0]), "r"(b[1]));
}

// ============================================================================
// Kernel 1: fused RHT (sign diag + 16-pt Hadamard) + NVFP4 quant-dequant -> bf16
// One thread per 16-element block. Single launch covers x then weight.
// /sqrt(16)=0.25 folded into scale + thresholds (exact power-of-2 scalings).
// ============================================================================
__global__ void __launch_bounds__(256) quant_rht_kernel(
    const float* __restrict__ inx, const float* __restrict__ inw,
    const float* __restrict__ signs,
    __nv_bfloat16* __restrict__ outx, __nv_bfloat16* __restrict__ outw,
    int nblk_x, int nblk_tot)
{
    int b = blockIdx.x * blockDim.x + threadIdx.x;
    if (b >= nblk_tot) return;

    const float* in;
    __nv_bfloat16* out;
    int bb;
    if (b < nblk_x) { in = inx; out = outx; bb = b; }
    else            { in = inw; out = outw; bb = b - nblk_x; }

    float v[16];
    const float4* p = reinterpret_cast<const float4*>(in) + (size_t)bb * 4;
    const float4* sp = reinterpret_cast<const float4*>(signs);
#pragma unroll
    for (int i = 0; i < 4; i++) {
        float4 t = p[i];
        float4 s = sp[i];
        v[4 * i + 0] = t.x * s.x; v[4 * i + 1] = t.y * s.y;
        v[4 * i + 2] = t.z * s.z; v[4 * i + 3] = t.w * s.w;
    }

    // Sylvester FWHT (matches np.block([[H,H],[H,-H]]) doubling); raw (un-normalized)
#pragma unroll
    for (int h = 1; h < 16; h <<= 1) {
#pragma unroll
        for (int i = 0; i < 16; i++) {
            if ((i & h) == 0) {
                float a = v[i], c = v[i + h];
                v[i] = a + c; v[i + h] = a - c;
            }
        }
    }
    float amax = 0.f;
#pragma unroll
    for (int i = 0; i < 16; i++) amax = fmaxf(amax, fabsf(v[i]));

    // scaled value = v*0.25 (exact). scale = e4m3(rn((amax*0.25)/6)).
    float scale = (float)__nv_fp8_e4m3(__fdiv_rn(amax * 0.25f, 6.0f));

    __nv_bfloat16 o[16];
    if (scale == 0.0f) {
#pragma unroll
        for (int i = 0; i < 16; i++) o[i] = __float2bfloat16_rn(0.0f);
    } else {
        // thresholds on RAW |v|: |v*0.25| > mid*scale <=> |v| > mid*scale*4 (exact x4)
        const float s4 = scale * 4.0f;
        const float t0 = 0.25f * s4, t1 = 0.75f * s4, t2 = 1.25f * s4,
                    t3 = 1.75f * s4, t4 = 2.5f * s4,  t5 = 3.5f * s4,
                    t6 = 5.0f * s4;
#pragma unroll
        for (int i = 0; i < 16; i++) {
            float av = fabsf(v[i]);
            float q = 0.0f;
            q = (av > t0) ? 0.5f : q;
            q = (av > t1) ? 1.0f : q;
            q = (av > t2) ? 1.5f : q;
            q = (av > t3) ? 2.0f : q;
            q = (av > t4) ? 3.0f : q;
            q = (av > t5) ? 4.0f : q;
            q = (av > t6) ? 6.0f : q;
            o[i] = __float2bfloat16_rn(copysignf(q * scale, v[i]));  // exact in bf16
        }
    }

    uint32_t w[8];
#pragma unroll
    for (int i = 0; i < 8; i++) {
        __nv_bfloat162 t = __halves2bfloat162(o[2 * i], o[2 * i + 1]);
        w[i] = *reinterpret_cast<uint32_t*>(&t);
    }
    uint4* dst = reinterpret_cast<uint4*>(out) + (size_t)bb * 2;
    dst[0] = make_uint4(w[0], w[1], w[2], w[3]);
    dst[1] = make_uint4(w[4], w[5], w[6], w[7]);
}

// ============================================================================
// Kernel 2: bf16 mma.sync GEMM  out[M,N] = A[M,K] * B[N,K]^T + bias
// R8 tile/occupancy (best measured): BM=BN=128, BK=64, 3 stages, occupancy 2,
// 8 warps 2(M)x4(N), warp tile 64x32, plain LDSM addressing.
// Producer: single-thread TMA (2 bulk loads/stage, expect_tx on count-1 full
// barrier). Consumer structure: R8's PROVEN end-of-iteration __syncthreads
// guards the stage anti-dependency (fill target (it+2)%3 == (it-1)%3, whose
// readers all passed the barrier at the end of it-1). No empty barriers.
// ============================================================================
static constexpr int BM = 128, BN = 128, BK = 64, NST = 3;
static constexpr uint32_t TILE_BYTES = 128 * 128;           // 16 KB
static constexpr uint32_t STAGE_BYTES = 2 * TILE_BYTES;     // A + B = 32 KB
static constexpr uint32_t OFF_FULL  = 0;                    // 3 x 8B
static constexpr uint32_t OFF_BIAS  = 64;                   // 128 floats -> 576
static constexpr uint32_t OFF_STAGE = 1024;                 // 1024-aligned stages
static constexpr uint32_t SMEM_USED = OFF_STAGE + NST * STAGE_BYTES;  // 99328
static constexpr uint32_t SMEM_DYN  = SMEM_USED + 1024;     // manual align slack

__global__ void __launch_bounds__(256, 2) gemm_bf16_kernel(
    const __grid_constant__ CUtensorMap tma_a,
    const __grid_constant__ CUtensorMap tma_b,
    const float* __restrict__ bias,
    float* __restrict__ out, int m_tiles)
{
    extern __shared__ char smem_raw[];
    char* sptr = (char*)((((uintptr_t)smem_raw) + 1023) & ~(uintptr_t)1023);
    const uint32_t sbase = smem_u32(sptr);
    float* sbias = reinterpret_cast<float*>(sptr + OFF_BIAS);

    const int tid = threadIdx.x;
    const int wid = tid >> 5, lane = tid & 31;
    const int wm = wid >> 2, wn = wid & 3;   // 2 x 4 warps, warp tile 64x32

    // CTA rasterization: supertiles of 16 mt x 16 nt (256 CTAs) for L2 reuse
    int bid = blockIdx.x;
    int mt_idx, nt_idx;
    if ((m_tiles & 15) == 0) {
        int s = bid >> 8, r = bid & 255;          // m_tiles=64, n_tiles=32 -> s in 0..7
        mt_idx = ((s & 3) << 4) | (r & 15);
        nt_idx = ((s >> 2) << 4) | (r >> 4);
    } else {
        mt_idx = bid % m_tiles;
        nt_idx = bid / m_tiles;
    }
    const int m0 = mt_idx * BM, n0 = nt_idx * BN;

    if (tid == 0) {
#pragma unroll
        for (int s = 0; s < NST; s++)
            mbar_init(sbase + OFF_FULL + 8 * s, 1);   // expect_tx is the sole arrive
        fence_proxy();
    }
    // bias -> smem
    if (tid < BN) sbias[tid] = bias[n0 + tid];
    __syncthreads();   // barriers + bias visible

    const int KCH = KDIM / BK;   // 64

    // ---- prologue: fill stages 0 and 1 ----
    if (tid == 0) {
#pragma unroll
        for (int s = 0; s < 2; s++) {
            uint32_t full = sbase + OFF_FULL + 8 * s;
            uint32_t dst  = sbase + OFF_STAGE + s * STAGE_BYTES;
            mbar_expect_tx(full, STAGE_BYTES);
            tma2d(dst,              &tma_a, s * BK, m0, full);
            tma2d(dst + TILE_BYTES, &tma_b, s * BK, n0, full);
        }
    }

    float c[4][4][4];
#pragma unroll
    for (int i = 0; i < 4; i++)
#pragma unroll
        for (int j = 0; j < 4; j++)
#pragma unroll
            for (int k = 0; k < 4; k++) c[i][j][k] = 0.f;

    // ldmatrix lane address components (R8 plain addressing)
    const int a_r_in16 = lane & 15;
    const int a_uoff   = lane >> 4;          // 0 or 1
    const int b_r_in16 = (lane & 7) + ((lane >> 4) << 3);
    const int b_uoff   = (lane >> 3) & 1;

    int cs = 0, cph = 0;    // consumer stage / full-barrier phase parity

#pragma unroll 1
    for (int it = 0; it < KCH; it++) {
        // ---- producer: refill stage (cs+2)%3 == stage consumed at it-1.
        // The __syncthreads at the end of it-1 guarantees its readers are done.
        if (tid == 0 && it + 2 < KCH) {
            int fs = cs + 2; if (fs >= NST) fs -= NST;
            uint32_t full = sbase + OFF_FULL + 8 * fs;
            uint32_t dst  = sbase + OFF_STAGE + fs * STAGE_BYTES;
            mbar_expect_tx(full, STAGE_BYTES);
            tma2d(dst,              &tma_a, (it + 2) * BK, m0, full);
            tma2d(dst + TILE_BYTES, &tma_b, (it + 2) * BK, n0, full);
        }

        // ---- consumer: wait stage cs full (acquire: TMA writes visible) ----
        mbar_wait(sbase + OFF_FULL + 8 * cs, (uint32_t)cph);

        uint32_t sa = sbase + OFF_STAGE + cs * STAGE_BYTES;
        uint32_t sb = sa + TILE_BYTES;

#pragma unroll
        for (int ks = 0; ks < 4; ks++) {
            uint32_t a[4][4], b2[2][4];
#pragma unroll
            for (int mt = 0; mt < 4; mt++) {
                int r = wm * 64 + mt * 16 + a_r_in16;
                int u = ks * 2 + a_uoff;
                ldmx4(a[mt], sa + r * 128 + ((u ^ (r & 7)) << 4));
            }
#pragma unroll
            for (int nh = 0; nh < 2; nh++) {
                int r = wn * 32 + nh * 16 + b_r_in16;
                int u = ks * 2 + b_uoff;
                ldmx4(b2[nh], sb + r * 128 + ((u ^ (r & 7)) << 4));
            }
#pragma unroll
            for (int mt = 0; mt < 4; mt++) {
#pragma unroll
                for (int nt = 0; nt < 4; nt++) {
                    const uint32_t bb[2] = { b2[nt >> 1][(nt & 1) * 2],
                                             b2[nt >> 1][(nt & 1) * 2 + 1] };
                    mma_bf16(c[mt][nt], a[mt], bb);
                }
            }
        }

        // all warps finished reading stage cs before anyone refills it
        __syncthreads();
        if (++cs == NST) { cs = 0; cph ^= 1; }
    }

    // ---- epilogue: direct float2 stores with bias ----
    const int er = lane >> 2;            // 0..7
    const int ec = (lane & 3) * 2;       // 0,2,4,6
#pragma unroll
    for (int mt = 0; mt < 4; mt++) {
        int row0 = m0 + wm * 64 + mt * 16 + er;
#pragma unroll
        for (int nt = 0; nt < 4; nt++) {
            int colL = wn * 32 + nt * 8 + ec;       // local col in [0,128)
            int col  = n0 + colL;
            float b0v = sbias[colL], b1v = sbias[colL + 1];
            float2 v0 = make_float2(c[mt][nt][0] + b0v, c[mt][nt][1] + b1v);
            float2 v1 = make_float2(c[mt][nt][2] + b0v, c[mt][nt][3] + b1v);
            *reinterpret_cast<float2*>(out + (size_t)row0 * NDIM + col) = v0;
            *reinterpret_cast<float2*>(out + (size_t)(row0 + 8) * NDIM + col) = v1;
        }
    }
}

// ============================================================================
// Host side
// ============================================================================
typedef CUresult (CUDAAPI *encode_fn_t)(
    CUtensorMap*, CUtensorMapDataType, cuuint32_t, void*,
    const cuuint64_t*, const cuuint64_t*, const cuuint32_t*, const cuuint32_t*,
    CUtensorMapInterleave, CUtensorMapSwizzle, CUtensorMapL2promotion,
    CUtensorMapFloatOOBfill);

static void make_map_bf16(encode_fn_t enc, CUtensorMap* tm, void* ptr,
                          uint64_t d0, uint64_t d1)
{
    cuuint64_t dims[2]    = {d0, d1};
    cuuint64_t strides[1] = {d0 * 2};      // bytes
    cuuint32_t box[2]     = {(cuuint32_t)BK, 128};   // 64 bf16 = 128B x 128 rows
    cuuint32_t es[2]      = {1, 1};
    enc(tm, CU_TENSOR_MAP_DATA_TYPE_BFLOAT16, 2, ptr, dims, strides, box, es,
        CU_TENSOR_MAP_INTERLEAVE_NONE, CU_TENSOR_MAP_SWIZZLE_128B,
        CU_TENSOR_MAP_L2_PROMOTION_L2_128B, CU_TENSOR_MAP_FLOAT_OOB_FILL_NONE);
}

extern "C" void kernel_launch(void* const* d_in, const int* in_sizes, int n_in,
                              void* d_out, int out_size)
{
    const float* x        = (const float*)d_in[0];
    const float* weight   = (const float*)d_in[1];
    const float* bias     = (const float*)d_in[2];
    const float* signs_in = (const float*)d_in[3];
    // d_in[4] = signs_grad: unused in forward

    const int K = KDIM, N = NDIM;
    const int M = in_sizes[0] / K;

    __nv_bfloat16 *xq = nullptr, *wq = nullptr;
    cudaGetSymbolAddress((void**)&xq, g_xq);
    cudaGetSymbolAddress((void**)&wq, g_wq);

    // --- quantize x and weight to bf16 scratch (single launch) ---
    int nblk_x = M * (K / 16);
    int nblk_w = N * (K / 16);
    int nblk_tot = nblk_x + nblk_w;
    quant_rht_kernel<<<(nblk_tot + 255) / 256, 256>>>(
        x, weight, signs_in, xq, wq, nblk_x, nblk_tot);

    // --- TMA descriptors (driver entry point via runtime; no -lcuda link) ---
    void* pfn = nullptr;
    cudaDriverEntryPointQueryResult qr;
    cudaGetDriverEntryPointByVersion("cuTensorMapEncodeTiled", &pfn, 12000,
                                     cudaEnableDefault, &qr);
    encode_fn_t enc = (encode_fn_t)pfn;

    CUtensorMap ta, tb;
    make_map_bf16(enc, &ta, xq, (uint64_t)K, (uint64_t)M);
    make_map_bf16(enc, &tb, wq, (uint64_t)K, (uint64_t)N);

    // --- GEMM ---
    static bool attr_set = false;
    if (!attr_set) {
        cudaFuncSetAttribute(gemm_bf16_kernel,
                             cudaFuncAttributeMaxDynamicSharedMemorySize, SMEM_DYN);
        attr_set = true;
    }
    int m_tiles = M / BM;            // 64
    int n_tiles = N / BN;            // 32
    gemm_bf16_kernel<<<m_tiles * n_tiles, 256, SMEM_DYN>>>(
        ta, tb, bias, (float*)d_out, m_tiles);
}

// round 15
// speedup vs baseline: 1.2007x; 1.0745x over previous
#include <cuda_runtime.h>
#include <cuda.h>
#include <cuda_bf16.h>
#include <cuda_fp8.h>
#include <cstdint>
#include <cstddef>

// ============================================================================
// Problem constants (shapes fixed by the dataset)
// ============================================================================
static constexpr int KDIM = 4096;   // inner dim
static constexpr int NDIM = 4096;   // out features
static constexpr int MMAX = 8192;   // 4*2048 rows

// bf16 scratch for quantized activations / weights (device globals: no alloc)
__device__ __align__(1024) __nv_bfloat16 g_xq[(size_t)MMAX * KDIM];
__device__ __align__(1024) __nv_bfloat16 g_wq[(size_t)NDIM * KDIM];

#define DINL static __device__ __forceinline__

DINL uint32_t smem_u32(const void* p) {
    uint32_t a;
    asm("{ .reg .u64 t; cvta.to.shared.u64 t, %1; cvt.u32.u64 %0, t; }"
        : "=r"(a) : "l"(p));
    return a;
}
DINL void mbar_init(uint32_t a, uint32_t cnt) {
    asm volatile("mbarrier.init.shared.b64 [%0], %1;" :: "r"(a), "r"(cnt) : "memory");
}
DINL void mbar_expect_tx(uint32_t a, uint32_t bytes) {
    asm volatile("mbarrier.arrive.expect_tx.shared.b64 _, [%0], %1;"
                 :: "r"(a), "r"(bytes) : "memory");
}
DINL void mbar_wait(uint32_t a, uint32_t parity) {
    asm volatile(
        "{\n\t.reg .pred P;\n\t"
        "LAB_W_%=:\n\t"
        "mbarrier.try_wait.parity.acquire.cta.shared::cta.b64 P, [%0], %1, 0x989680;\n\t"
        "@P bra LAB_D_%=;\n\t"
        "bra LAB_W_%=;\n\t"
        "LAB_D_%=:\n\t}"
        :: "r"(a), "r"(parity) : "memory");
}
DINL void tma2d(uint32_t dst, const CUtensorMap* tm, int cx, int cy, uint32_t bar) {
    asm volatile(
        "cp.async.bulk.tensor.2d.shared::cta.global.tile.mbarrier::complete_tx::bytes "
        "[%0], [%1, {%2, %3}], [%4];"
        :: "r"(dst), "l"(tm), "r"(cx), "r"(cy), "r"(bar) : "memory");
}
DINL void fence_proxy() { asm volatile("fence.proxy.async.shared::cta;" ::: "memory"); }

DINL void ldmx4(uint32_t* r, uint32_t addr) {
    asm volatile("ldmatrix.sync.aligned.m8n8.x4.shared.b16 {%0,%1,%2,%3}, [%4];"
                 : "=r"(r[0]), "=r"(r[1]), "=r"(r[2]), "=r"(r[3]) : "r"(addr));
}
DINL void mma_bf16(float* c, const uint32_t* a, const uint32_t* b) {
    asm volatile(
        "mma.sync.aligned.m16n8k16.row.col.f32.bf16.bf16.f32 "
        "{%0,%1,%2,%3}, {%4,%5,%6,%7}, {%8,%9}, {%0,%1,%2,%3};"
        : "+f"(c[0]), "+f"(c[1]), "+f"(c[2]), "+f"(c[3])
        : "r"(a[0]), "r"(a[1]), "r"(a[2]), "r"(a[3]), "r"(b[0]), "r"(b[1]));
}

// ============================================================================
// Kernel 1: fused RHT (sign diag + 16-pt Hadamard) + NVFP4 quant-dequant -> bf16
// One thread per 16-element block. Single launch covers x then weight.
// /sqrt(16)=0.25 folded into scale + thresholds (exact power-of-2 scalings).
// ============================================================================
__global__ void __launch_bounds__(256) quant_rht_kernel(
    const float* __restrict__ inx, const float* __restrict__ inw,
    const float* __restrict__ signs,
    __nv_bfloat16* __restrict__ outx, __nv_bfloat16* __restrict__ outw,
    int nblk_x, int nblk_tot)
{
    int b = blockIdx.x * blockDim.x + threadIdx.x;
    if (b >= nblk_tot) return;

    const float* in;
    __nv_bfloat16* out;
    int bb;
    if (b < nblk_x) { in = inx; out = outx; bb = b; }
    else            { in = inw; out = outw; bb = b - nblk_x; }

    float v[16];
    const float4* p = reinterpret_cast<const float4*>(in) + (size_t)bb * 4;
    const float4* sp = reinterpret_cast<const float4*>(signs);
#pragma unroll
    for (int i = 0; i < 4; i++) {
        float4 t = p[i];
        float4 s = sp[i];
        v[4 * i + 0] = t.x * s.x; v[4 * i + 1] = t.y * s.y;
        v[4 * i + 2] = t.z * s.z; v[4 * i + 3] = t.w * s.w;
    }

    // Sylvester FWHT (matches np.block([[H,H],[H,-H]]) doubling); raw (un-normalized)
#pragma unroll
    for (int h = 1; h < 16; h <<= 1) {
#pragma unroll
        for (int i = 0; i < 16; i++) {
            if ((i & h) == 0) {
                float a = v[i], c = v[i + h];
                v[i] = a + c; v[i + h] = a - c;
            }
        }
    }
    float amax = 0.f;
#pragma unroll
    for (int i = 0; i < 16; i++) amax = fmaxf(amax, fabsf(v[i]));

    // scaled value = v*0.25 (exact). scale = e4m3(rn((amax*0.25)/6)).
    float scale = (float)__nv_fp8_e4m3(__fdiv_rn(amax * 0.25f, 6.0f));

    __nv_bfloat16 o[16];
    if (scale == 0.0f) {
#pragma unroll
        for (int i = 0; i < 16; i++) o[i] = __float2bfloat16_rn(0.0f);
    } else {
        // thresholds on RAW |v|: |v*0.25| > mid*scale <=> |v| > mid*scale*4 (exact x4)
        const float s4 = scale * 4.0f;
        const float t0 = 0.25f * s4, t1 = 0.75f * s4, t2 = 1.25f * s4,
                    t3 = 1.75f * s4, t4 = 2.5f * s4,  t5 = 3.5f * s4,
                    t6 = 5.0f * s4;
#pragma unroll
        for (int i = 0; i < 16; i++) {
            float av = fabsf(v[i]);
            float q = 0.0f;
            q = (av > t0) ? 0.5f : q;
            q = (av > t1) ? 1.0f : q;
            q = (av > t2) ? 1.5f : q;
            q = (av > t3) ? 2.0f : q;
            q = (av > t4) ? 3.0f : q;
            q = (av > t5) ? 4.0f : q;
            q = (av > t6) ? 6.0f : q;
            o[i] = __float2bfloat16_rn(copysignf(q * scale, v[i]));  // exact in bf16
        }
    }

    uint32_t w[8];
#pragma unroll
    for (int i = 0; i < 8; i++) {
        __nv_bfloat162 t = __halves2bfloat162(o[2 * i], o[2 * i + 1]);
        w[i] = *reinterpret_cast<uint32_t*>(&t);
    }
    uint4* dst = reinterpret_cast<uint4*>(out) + (size_t)bb * 2;
    dst[0] = make_uint4(w[0], w[1], w[2], w[3]);
    dst[1] = make_uint4(w[4], w[5], w[6], w[7]);
}

// ============================================================================
// Kernel 2: bf16 mma.sync GEMM  out[M,N] = A[M,K] * B[N,K]^T + bias
// R14 structure (best measured): BM=BN=128, BK=64, 3 stages, occupancy 2,
// 8 warps 2(M)x4(N), TMA producer + end-of-iteration __syncthreads guard.
// NEW: ks0 fragments of the NEXT stage are preloaded BEFORE the barrier
// (its full-barrier completed 2 iterations ago), so post-barrier the warps
// issue 16 MMAs immediately instead of stalling on a fresh LDSM burst.
// Hazard: preload reads stage (it+1)%3; next fill targets (it+2)%3 — disjoint.
// ============================================================================
static constexpr int BM = 128, BN = 128, BK = 64, NST = 3;
static constexpr uint32_t TILE_BYTES = 128 * 128;           // 16 KB
static constexpr uint32_t STAGE_BYTES = 2 * TILE_BYTES;     // A + B = 32 KB
static constexpr uint32_t OFF_FULL  = 0;                    // 3 x 8B
static constexpr uint32_t OFF_BIAS  = 64;                   // 128 floats -> 576
static constexpr uint32_t OFF_STAGE = 1024;                 // 1024-aligned stages
static constexpr uint32_t SMEM_USED = OFF_STAGE + NST * STAGE_BYTES;  // 99328
static constexpr uint32_t SMEM_DYN  = SMEM_USED + 1024;     // manual align slack

__global__ void __launch_bounds__(256, 2) gemm_bf16_kernel(
    const __grid_constant__ CUtensorMap tma_a,
    const __grid_constant__ CUtensorMap tma_b,
    const float* __restrict__ bias,
    float* __restrict__ out, int m_tiles)
{
    extern __shared__ char smem_raw[];
    char* sptr = (char*)((((uintptr_t)smem_raw) + 1023) & ~(uintptr_t)1023);
    const uint32_t sbase = smem_u32(sptr);
    float* sbias = reinterpret_cast<float*>(sptr + OFF_BIAS);

    const int tid = threadIdx.x;
    const int wid = tid >> 5, lane = tid & 31;
    const int wm = wid >> 2, wn = wid & 3;   // 2 x 4 warps, warp tile 64x32

    // CTA rasterization: supertiles of 16 mt x 16 nt (256 CTAs) for L2 reuse
    int bid = blockIdx.x;
    int mt_idx, nt_idx;
    if ((m_tiles & 15) == 0) {
        int s = bid >> 8, r = bid & 255;          // m_tiles=64, n_tiles=32 -> s in 0..7
        mt_idx = ((s & 3) << 4) | (r & 15);
        nt_idx = ((s >> 2) << 4) | (r >> 4);
    } else {
        mt_idx = bid % m_tiles;
        nt_idx = bid / m_tiles;
    }
    const int m0 = mt_idx * BM, n0 = nt_idx * BN;

    if (tid == 0) {
#pragma unroll
        for (int s = 0; s < NST; s++)
            mbar_init(sbase + OFF_FULL + 8 * s, 1);   // expect_tx is the sole arrive
        fence_proxy();
    }
    // bias -> smem
    if (tid < BN) sbias[tid] = bias[n0 + tid];
    __syncthreads();   // barriers + bias visible

    const int KCH = KDIM / BK;   // 64

    // ---- prologue: fill stages 0 and 1 ----
    if (tid == 0) {
#pragma unroll
        for (int s = 0; s < 2; s++) {
            uint32_t full = sbase + OFF_FULL + 8 * s;
            uint32_t dst  = sbase + OFF_STAGE + s * STAGE_BYTES;
            mbar_expect_tx(full, STAGE_BYTES);
            tma2d(dst,              &tma_a, s * BK, m0, full);
            tma2d(dst + TILE_BYTES, &tma_b, s * BK, n0, full);
        }
    }

    float c[4][4][4];
#pragma unroll
    for (int i = 0; i < 4; i++)
#pragma unroll
        for (int j = 0; j < 4; j++)
#pragma unroll
            for (int k = 0; k < 4; k++) c[i][j][k] = 0.f;

    // ldmatrix lane address components (plain addressing, proven)
    const int a_r_in16 = lane & 15;
    const int a_uoff   = lane >> 4;          // 0 or 1
    const int b_r_in16 = (lane & 7) + ((lane >> 4) << 3);
    const int b_uoff   = (lane >> 3) & 1;

    // persistent fragment arrays (preloaded for ks0, reused for ks1..3)
    uint32_t a[4][4], b2[2][4];

    // fragment load for (stage base sa/sb, k-step ks)
    auto load_frags = [&](uint32_t sa, uint32_t sb, int ks) {
#pragma unroll
        for (int mt = 0; mt < 4; mt++) {
            int r = wm * 64 + mt * 16 + a_r_in16;
            int u = ks * 2 + a_uoff;
            ldmx4(a[mt], sa + r * 128 + ((u ^ (r & 7)) << 4));
        }
#pragma unroll
        for (int nh = 0; nh < 2; nh++) {
            int r = wn * 32 + nh * 16 + b_r_in16;
            int u = ks * 2 + b_uoff;
            ldmx4(b2[nh], sb + r * 128 + ((u ^ (r & 7)) << 4));
        }
    };

    int cs = 0, cph = 0;    // consumer stage / full-barrier phase parity

    // initial: wait stage 0 full, preload its ks0 fragments
    mbar_wait(sbase + OFF_FULL + 0, 0u);
    load_frags(sbase + OFF_STAGE, sbase + OFF_STAGE + TILE_BYTES, 0);

#pragma unroll 1
    for (int it = 0; it < KCH; it++) {
        // ---- producer: refill stage (it+2)%3 == stage consumed at it-1.
        // The __syncthreads at the end of it-1 guarantees its readers are done.
        if (tid == 0 && it + 2 < KCH) {
            int fs = cs + 2; if (fs >= NST) fs -= NST;
            uint32_t full = sbase + OFF_FULL + 8 * fs;
            uint32_t dst  = sbase + OFF_STAGE + fs * STAGE_BYTES;
            mbar_expect_tx(full, STAGE_BYTES);
            tma2d(dst,              &tma_a, (it + 2) * BK, m0, full);
            tma2d(dst + TILE_BYTES, &tma_b, (it + 2) * BK, n0, full);
        }

        uint32_t sa = sbase + OFF_STAGE + cs * STAGE_BYTES;
        uint32_t sb = sa + TILE_BYTES;

        // ks=0: MMAs from preloaded fragments; then ks=1..3 reload in place
#pragma unroll
        for (int ks = 0; ks < 4; ks++) {
#pragma unroll
            for (int mt = 0; mt < 4; mt++) {
#pragma unroll
                for (int nt = 0; nt < 4; nt++) {
                    const uint32_t bb[2] = { b2[nt >> 1][(nt & 1) * 2],
                                             b2[nt >> 1][(nt & 1) * 2 + 1] };
                    mma_bf16(c[mt][nt], a[mt], bb);
                }
            }
            if (ks < 3) load_frags(sa, sb, ks + 1);
        }

        // ---- preload next stage's ks0 fragments BEFORE the barrier ----
        if (it + 1 < KCH) {
            int ns = cs + 1; if (ns >= NST) ns -= NST;
            uint32_t nph = (cs == NST - 1) ? (uint32_t)(cph ^ 1) : (uint32_t)cph;
            mbar_wait(sbase + OFF_FULL + 8 * ns, nph);   // fast path: prefetched
            uint32_t nsa = sbase + OFF_STAGE + ns * STAGE_BYTES;
            load_frags(nsa, nsa + TILE_BYTES, 0);
        }

        // all warps finished reading stage cs (and preloading ns) before the
        // next iteration's producer refills stage (it+3)%3 == cs
        __syncthreads();
        if (++cs == NST) { cs = 0; cph ^= 1; }
    }

    // ---- epilogue: direct float2 stores with bias ----
    const int er = lane >> 2;            // 0..7
    const int ec = (lane & 3) * 2;       // 0,2,4,6
#pragma unroll
    for (int mt = 0; mt < 4; mt++) {
        int row0 = m0 + wm * 64 + mt * 16 + er;
#pragma unroll
        for (int nt = 0; nt < 4; nt++) {
            int colL = wn * 32 + nt * 8 + ec;       // local col in [0,128)
            int col  = n0 + colL;
            float b0v = sbias[colL], b1v = sbias[colL + 1];
            float2 v0 = make_float2(c[mt][nt][0] + b0v, c[mt][nt][1] + b1v);
            float2 v1 = make_float2(c[mt][nt][2] + b0v, c[mt][nt][3] + b1v);
            *reinterpret_cast<float2*>(out + (size_t)row0 * NDIM + col) = v0;
            *reinterpret_cast<float2*>(out + (size_t)(row0 + 8) * NDIM + col) = v1;
        }
    }
}

// ============================================================================
// Host side
// ============================================================================
typedef CUresult (CUDAAPI *encode_fn_t)(
    CUtensorMap*, CUtensorMapDataType, cuuint32_t, void*,
    const cuuint64_t*, const cuuint64_t*, const cuuint32_t*, const cuuint32_t*,
    CUtensorMapInterleave, CUtensorMapSwizzle, CUtensorMapL2promotion,
    CUtensorMapFloatOOBfill);

static void make_map_bf16(encode_fn_t enc, CUtensorMap* tm, void* ptr,
                          uint64_t d0, uint64_t d1)
{
    cuuint64_t dims[2]    = {d0, d1};
    cuuint64_t strides[1] = {d0 * 2};      // bytes
    cuuint32_t box[2]     = {(cuuint32_t)BK, 128};   // 64 bf16 = 128B x 128 rows
    cuuint32_t es[2]      = {1, 1};
    enc(tm, CU_TENSOR_MAP_DATA_TYPE_BFLOAT16, 2, ptr, dims, strides, box, es,
        CU_TENSOR_MAP_INTERLEAVE_NONE, CU_TENSOR_MAP_SWIZZLE_128B,
        CU_TENSOR_MAP_L2_PROMOTION_L2_128B, CU_TENSOR_MAP_FLOAT_OOB_FILL_NONE);
}

extern "C" void kernel_launch(void* const* d_in, const int* in_sizes, int n_in,
                              void* d_out, int out_size)
{
    const float* x        = (const float*)d_in[0];
    const float* weight   = (const float*)d_in[1];
    const float* bias     = (const float*)d_in[2];
    const float* signs_in = (const float*)d_in[3];
    // d_in[4] = signs_grad: unused in forward

    const int K = KDIM, N = NDIM;
    const int M = in_sizes[0] / K;

    __nv_bfloat16 *xq = nullptr, *wq = nullptr;
    cudaGetSymbolAddress((void**)&xq, g_xq);
    cudaGetSymbolAddress((void**)&wq, g_wq);

    // --- quantize x and weight to bf16 scratch (single launch) ---
    int nblk_x = M * (K / 16);
    int nblk_w = N * (K / 16);
    int nblk_tot = nblk_x + nblk_w;
    quant_rht_kernel<<<(nblk_tot + 255) / 256, 256>>>(
        x, weight, signs_in, xq, wq, nblk_x, nblk_tot);

    // --- TMA descriptors (driver entry point via runtime; no -lcuda link) ---
    void* pfn = nullptr;
    cudaDriverEntryPointQueryResult qr;
    cudaGetDriverEntryPointByVersion("cuTensorMapEncodeTiled", &pfn, 12000,
                                     cudaEnableDefault, &qr);
    encode_fn_t enc = (encode_fn_t)pfn;

    CUtensorMap ta, tb;
    make_map_bf16(enc, &ta, xq, (uint64_t)K, (uint64_t)M);
    make_map_bf16(enc, &tb, wq, (uint64_t)K, (uint64_t)N);

    // --- GEMM ---
    static bool attr_set = false;
    if (!attr_set) {
        cudaFuncSetAttribute(gemm_bf16_kernel,
                             cudaFuncAttributeMaxDynamicSharedMemorySize, SMEM_DYN);
        attr_set = true;
    }
    int m_tiles = M / BM;            // 64
    int n_tiles = N / BN;            // 32
    gemm_bf16_kernel<<<m_tiles * n_tiles, 256, SMEM_DYN>>>(
        ta, tb, bias, (float*)d_out, m_tiles);
}